// round 1
// baseline (speedup 1.0000x reference)
#include <cuda_runtime.h>
#include <cstdint>

// Problem constants (fixed by the reference)
#define Bc 128
#define Tc 30
#define Nc 10000
#define Mc 5000
#define Kc 10
#define CHK_W 6
#define OBS_W 50
#define EPSc 1e-6f
#define LN2f 0.69314718055994530942f

#define NTHREADS 512
#define ROWS 4
#define NCHUNKS ((Tc + ROWS - 1) / ROWS)   // 8

// Shared memory layout (bytes)
#define OFF_TANH4   0
#define SZ_TANH4    (Nc * 16)              // 160000: float4 per position
#define OFF_CIDX    (OFF_TANH4 + SZ_TANH4) // 160000
#define SZ_CIDX     (Mc * CHK_W * 2)       // 60000 u16
#define OFF_OIDX    (OFF_CIDX + SZ_CIDX)   // 220000
#define SZ_OIDX     (Kc * OBS_W * 2)       // 1000 u16
#define OFF_RED     ((OFF_OIDX + SZ_OIDX + 15) & ~15) // 221008
#define SZ_RED      (NTHREADS / 32 * 4)    // 64
#define SMEM_BYTES  (OFF_RED + SZ_RED)     // ~221072

__device__ double g_acc;

__device__ __forceinline__ float tanh_half(float x) {
    // tanh(x/2) = 1 - 2/(exp(x)+1)
    float e = __expf(x);
    return 1.0f - __fdividef(2.0f, e + 1.0f);
}

__global__ void zero_kernel() { g_acc = 0.0; }

__global__ void finalize_kernel(float* out) {
    out[0] = (float)(g_acc * (1.0 / ((double)Bc * (double)Tc)));
}

__global__ __launch_bounds__(NTHREADS, 1)
void decode_loss_kernel(const float* __restrict__ llrs,
                        const int* __restrict__ syndromes,
                        const int* __restrict__ observables,
                        const int* __restrict__ chk_idx,
                        const int* __restrict__ obs_idx) {
    extern __shared__ char smem[];
    float4*         tanh4 = (float4*)(smem + OFF_TANH4);
    unsigned short* cidx  = (unsigned short*)(smem + OFF_CIDX);
    unsigned short* oidx  = (unsigned short*)(smem + OFF_OIDX);
    float*          red   = (float*)(smem + OFF_RED);

    const int b     = blockIdx.y;
    const int t0    = blockIdx.x * ROWS;
    const int nrows = min(ROWS, Tc - t0);
    const int tid   = threadIdx.x;

    // ---- Phase 1: load LLR rows, tanh, store float4-interleaved ----
    const float* rowbase = llrs + ((size_t)b * Tc + t0) * Nc;
    for (int i = tid; i < Nc; i += NTHREADS) {
        float4 v;
        v.x = tanh_half(rowbase[i]);
        v.y = (nrows > 1) ? tanh_half(rowbase[Nc + i])     : 0.0f;
        v.z = (nrows > 2) ? tanh_half(rowbase[2 * Nc + i]) : 0.0f;
        v.w = (nrows > 3) ? tanh_half(rowbase[3 * Nc + i]) : 0.0f;
        tanh4[i] = v;
    }

    // ---- Stage indices in smem as u16 (vectorized int4 reads) ----
    {
        const int4* c4 = (const int4*)chk_idx;
        ushort4* s4 = (ushort4*)cidx;
        for (int i = tid; i < (Mc * CHK_W) / 4; i += NTHREADS) {
            int4 v = c4[i];
            ushort4 u;
            u.x = (unsigned short)v.x; u.y = (unsigned short)v.y;
            u.z = (unsigned short)v.z; u.w = (unsigned short)v.w;
            s4[i] = u;
        }
        for (int i = tid; i < Kc * OBS_W; i += NTHREADS)
            oidx[i] = (unsigned short)obs_idx[i];
    }
    __syncthreads();

    const unsigned int* cidx32 = (const unsigned int*)cidx;
    const int* syn_row = syndromes + (size_t)b * Mc;

    float acc_chk = 0.0f;

    // ---- Phase 2: check loop (M=5000 checks, 6-wide products, 4 rows at once) ----
    for (int m = tid; m < Mc; m += NTHREADS) {
        unsigned int a0 = cidx32[3 * m];
        unsigned int a1 = cidx32[3 * m + 1];
        unsigned int a2 = cidx32[3 * m + 2];
        int i0 = a0 & 0xFFFF, i1 = a0 >> 16;
        int i2 = a1 & 0xFFFF, i3 = a1 >> 16;
        int i4 = a2 & 0xFFFF, i5 = a2 >> 16;

        float4 t0v = tanh4[i0];
        float4 t1v = tanh4[i1];
        float4 t2v = tanh4[i2];
        float4 t3v = tanh4[i3];
        float4 t4v = tanh4[i4];
        float4 t5v = tanh4[i5];

        // tree product, componentwise
        float px = (t0v.x * t1v.x) * (t2v.x * t3v.x) * (t4v.x * t5v.x);
        float py = (t0v.y * t1v.y) * (t2v.y * t3v.y) * (t4v.y * t5v.y);
        float pz = (t0v.z * t1v.z) * (t2v.z * t3v.z) * (t4v.z * t5v.z);
        float pw = (t0v.w * t1v.w) * (t2v.w * t3v.w) * (t4v.w * t5v.w);

        const int y = __ldg(&syn_row[m]);

        float pr[4] = {px, py, pz, pw};
        #pragma unroll
        for (int r = 0; r < ROWS; r++) {
            if (r < nrows) {
                float q = fminf(fmaxf(pr[r], -1.0f + EPSc), 1.0f - EPSc);
                float arg = y ? (1.0f - q) : (1.0f + q);
                // ln2 - ln(arg) = ln2 * (1 - log2(arg))
                acc_chk += LN2f * (1.0f - __log2f(arg));
            }
        }
    }

    // ---- Phase 3: observable loop (K=10, 50-wide products) ----
    float acc_obs = 0.0f;
    if (tid < Kc) {
        float4 pa = make_float4(1.f, 1.f, 1.f, 1.f);
        float4 pb = make_float4(1.f, 1.f, 1.f, 1.f);
        #pragma unroll
        for (int j = 0; j < OBS_W; j += 2) {
            float4 u = tanh4[oidx[tid * OBS_W + j]];
            float4 v = tanh4[oidx[tid * OBS_W + j + 1]];
            pa.x *= u.x; pa.y *= u.y; pa.z *= u.z; pa.w *= u.w;
            pb.x *= v.x; pb.y *= v.y; pb.z *= v.z; pb.w *= v.w;
        }
        float pr[4] = {pa.x * pb.x, pa.y * pb.y, pa.z * pb.z, pa.w * pb.w};
        const int y = __ldg(&observables[(size_t)b * Kc + tid]);
        #pragma unroll
        for (int r = 0; r < ROWS; r++) {
            if (r < nrows) {
                float q = fminf(fmaxf(pr[r], -1.0f + EPSc), 1.0f - EPSc);
                float arg = y ? (1.0f - q) : (1.0f + q);
                acc_obs += LN2f * (1.0f - __log2f(arg));
            }
        }
    }

    // ---- Block reduction (BETA = 0.5 for both halves) ----
    float v = 0.5f * (acc_chk + acc_obs);
    #pragma unroll
    for (int o = 16; o; o >>= 1) v += __shfl_down_sync(0xFFFFFFFFu, v, o);
    const int wid = tid >> 5, lane = tid & 31;
    if (lane == 0) red[wid] = v;
    __syncthreads();
    if (wid == 0) {
        float w = (lane < NTHREADS / 32) ? red[lane] : 0.0f;
        #pragma unroll
        for (int o = 8; o; o >>= 1) w += __shfl_down_sync(0xFFFFFFFFu, w, o);
        if (lane == 0) atomicAdd(&g_acc, (double)w);
    }
}

extern "C" void kernel_launch(void* const* d_in, const int* in_sizes, int n_in,
                              void* d_out, int out_size) {
    const float* llrs        = (const float*)d_in[0];
    const int*   syndromes   = (const int*)d_in[1];
    const int*   observables = (const int*)d_in[2];
    const int*   chk_idx     = (const int*)d_in[3];
    // d_in[4] = chk_seg (implied by layout), d_in[5] = obs_idx, d_in[6] = obs_seg
    const int*   obs_idx     = (const int*)d_in[5];
    float* out = (float*)d_out;

    cudaFuncSetAttribute(decode_loss_kernel,
                         cudaFuncAttributeMaxDynamicSharedMemorySize, SMEM_BYTES);

    zero_kernel<<<1, 1>>>();
    dim3 grid(NCHUNKS, Bc);
    decode_loss_kernel<<<grid, NTHREADS, SMEM_BYTES>>>(
        llrs, syndromes, observables, chk_idx, obs_idx);
    finalize_kernel<<<1, 1>>>(out);
}

// round 2
// speedup vs baseline: 3.4013x; 3.4013x over previous
#include <cuda_runtime.h>
#include <cuda_fp16.h>
#include <cstdint>

// Problem constants (fixed by the reference)
#define Bc 128
#define Tc 30
#define Nc 10000
#define Mc 5000
#define Kc 10
#define CHK_W 6
#define OBS_W 50
#define EPSc 1e-6f

#define NTHREADS 512
#define ROWS 8
#define NCHUNKS 4                 // ceil(30/8)
#define GRID (Bc * NCHUNKS)       // 512 CTAs
#define NQ (Nc / 4)               // 2500 positions per j-plane

// Shared memory layout (bytes)
// tanh table: 4 planes (j = n mod 4) x 2500 uint4 (8 fp16 rows per position)
#define OFF_T8   0
#define SZ_T8    (Nc * 16)                  // 160000
#define OFF_CIDX (OFF_T8 + SZ_T8)           // 160000
#define SZ_CIDX  (Mc * CHK_W * 2)           // 60000 u16 (pre-transformed)
#define OFF_OIDX (OFF_CIDX + SZ_CIDX)       // 220000
#define SZ_OIDX  (Kc * OBS_W * 2)           // 1000 u16
#define OFF_RED  ((OFF_OIDX + SZ_OIDX + 15) & ~15)   // 221008
#define SMEM_BYTES (OFF_RED + 64)           // ~221072

__device__ double g_acc = 0.0;
__device__ unsigned int g_cnt = 0;

__device__ __forceinline__ float tanh_half_f(float x) {
    // tanh(x/2) = 1 - 2/(exp(x)+1)   (2 MUFU: EX2 + RCP)
    float e = __expf(x);
    return 1.0f - __fdividef(2.0f, e + 1.0f);
}

__device__ __forceinline__ __half2 H2(unsigned int u) {
    return *reinterpret_cast<const __half2*>(&u);
}
__device__ __forceinline__ unsigned int U2(__half2 h) {
    return *reinterpret_cast<const unsigned int*>(&h);
}

__global__ __launch_bounds__(NTHREADS, 1)
void decode_loss_kernel(const float* __restrict__ llrs,
                        const int* __restrict__ syndromes,
                        const int* __restrict__ observables,
                        const int* __restrict__ chk_idx,
                        const int* __restrict__ obs_idx,
                        float* __restrict__ out) {
    extern __shared__ char smem[];
    uint4*          t8   = (uint4*)(smem + OFF_T8);
    unsigned short* cidx = (unsigned short*)(smem + OFF_CIDX);
    unsigned short* oidx = (unsigned short*)(smem + OFF_OIDX);
    float*          red  = (float*)(smem + OFF_RED);

    const int b     = blockIdx.y;
    const int t0    = blockIdx.x * ROWS;
    const int nrows = min(ROWS, Tc - t0);
    const int tid   = threadIdx.x;

    // ---- Stage indices, pre-transformed to plane layout:
    //      position n lives at plane (n&3), slot (n>>2) -> linear (n&3)*NQ + (n>>2)
    for (int i = tid; i < Mc * CHK_W; i += NTHREADS) {
        int v = __ldg(&chk_idx[i]);
        cidx[i] = (unsigned short)((v & 3) * NQ + (v >> 2));
    }
    for (int i = tid; i < Kc * OBS_W; i += NTHREADS) {
        int v = __ldg(&obs_idx[i]);
        oidx[i] = (unsigned short)((v & 3) * NQ + (v >> 2));
    }

    // ---- Phase 1: load 8 LLR rows as float4, tanh, pack 8 fp16 per position ----
    const float4* rb = (const float4*)(llrs + ((size_t)(b * Tc + t0)) * Nc);
    for (int q = tid; q < NQ; q += NTHREADS) {
        float4 v[ROWS];
        #pragma unroll
        for (int r = 0; r < ROWS; r++) {
            v[r] = (r < nrows) ? __ldg(&rb[(size_t)r * NQ + q])
                               : make_float4(0.f, 0.f, 0.f, 0.f);
        }
        #pragma unroll
        for (int r = 0; r < ROWS; r++) {
            v[r].x = tanh_half_f(v[r].x);
            v[r].y = tanh_half_f(v[r].y);
            v[r].z = tanh_half_f(v[r].z);
            v[r].w = tanh_half_f(v[r].w);
        }
        const float* vf = (const float*)v;   // vf[4*r + j] = component j of row r
        #pragma unroll
        for (int j = 0; j < 4; j++) {
            uint4 o;
            o.x = U2(__floats2half2_rn(vf[0*4 + j], vf[1*4 + j]));
            o.y = U2(__floats2half2_rn(vf[2*4 + j], vf[3*4 + j]));
            o.z = U2(__floats2half2_rn(vf[4*4 + j], vf[5*4 + j]));
            o.w = U2(__floats2half2_rn(vf[6*4 + j], vf[7*4 + j]));
            t8[j * NQ + q] = o;   // conflict-free STS: lanes stride 16B within a plane
        }
    }
    __syncthreads();

    const unsigned int* c32 = (const unsigned int*)cidx;
    const int* syn = syndromes + (size_t)b * Mc;

    // Accumulate S = sum of log2(arg); loss term = ln2 - ln2*log2(arg).
    // Padded rows have tanh=0 -> p=0 -> arg=1 -> log2=0: accumulate all 8 rows
    // unconditionally; the ln2 constant count is folded in analytically at the end.
    float acc = 0.0f;

    // ---- Phase 2: check loop (M=5000, 6-wide products, 8 rows per LDS.128) ----
    for (int m = tid; m < Mc; m += NTHREADS) {
        unsigned int a0 = c32[3 * m];
        unsigned int a1 = c32[3 * m + 1];
        unsigned int a2 = c32[3 * m + 2];
        uint4 g0 = t8[a0 & 0xFFFF];
        uint4 g1 = t8[a0 >> 16];
        uint4 g2 = t8[a1 & 0xFFFF];
        uint4 g3 = t8[a1 >> 16];
        uint4 g4 = t8[a2 & 0xFFFF];
        uint4 g5 = t8[a2 >> 16];
        const int y = __ldg(&syn[m]);
        const float s = y ? -1.0f : 1.0f;

        __half2 p0 = __hmul2(__hmul2(H2(g0.x), H2(g1.x)),
                     __hmul2(__hmul2(H2(g2.x), H2(g3.x)), __hmul2(H2(g4.x), H2(g5.x))));
        __half2 p1 = __hmul2(__hmul2(H2(g0.y), H2(g1.y)),
                     __hmul2(__hmul2(H2(g2.y), H2(g3.y)), __hmul2(H2(g4.y), H2(g5.y))));
        __half2 p2 = __hmul2(__hmul2(H2(g0.z), H2(g1.z)),
                     __hmul2(__hmul2(H2(g2.z), H2(g3.z)), __hmul2(H2(g4.z), H2(g5.z))));
        __half2 p3 = __hmul2(__hmul2(H2(g0.w), H2(g1.w)),
                     __hmul2(__hmul2(H2(g2.w), H2(g3.w)), __hmul2(H2(g4.w), H2(g5.w))));

        float2 f0 = __half22float2(p0);
        float2 f1 = __half22float2(p1);
        float2 f2 = __half22float2(p2);
        float2 f3 = __half22float2(p3);

        acc += __log2f(fmaxf(fmaf(s, f0.x, 1.0f), EPSc));
        acc += __log2f(fmaxf(fmaf(s, f0.y, 1.0f), EPSc));
        acc += __log2f(fmaxf(fmaf(s, f1.x, 1.0f), EPSc));
        acc += __log2f(fmaxf(fmaf(s, f1.y, 1.0f), EPSc));
        acc += __log2f(fmaxf(fmaf(s, f2.x, 1.0f), EPSc));
        acc += __log2f(fmaxf(fmaf(s, f2.y, 1.0f), EPSc));
        acc += __log2f(fmaxf(fmaf(s, f3.x, 1.0f), EPSc));
        acc += __log2f(fmaxf(fmaf(s, f3.y, 1.0f), EPSc));
    }

    // ---- Phase 3: observable loop (K=10, 50-wide products) ----
    if (tid < Kc) {
        const __half2 one2 = __float2half2_rn(1.0f);
        __half2 q0 = one2, q1 = one2, q2 = one2, q3 = one2;
        #pragma unroll
        for (int j = 0; j < OBS_W; j++) {
            uint4 g = t8[oidx[tid * OBS_W + j]];
            q0 = __hmul2(q0, H2(g.x));
            q1 = __hmul2(q1, H2(g.y));
            q2 = __hmul2(q2, H2(g.z));
            q3 = __hmul2(q3, H2(g.w));
        }
        const int y = __ldg(&observables[(size_t)b * Kc + tid]);
        const float s = y ? -1.0f : 1.0f;
        float2 f0 = __half22float2(q0);
        float2 f1 = __half22float2(q1);
        float2 f2 = __half22float2(q2);
        float2 f3 = __half22float2(q3);
        acc += __log2f(fmaxf(fmaf(s, f0.x, 1.0f), EPSc));
        acc += __log2f(fmaxf(fmaf(s, f0.y, 1.0f), EPSc));
        acc += __log2f(fmaxf(fmaf(s, f1.x, 1.0f), EPSc));
        acc += __log2f(fmaxf(fmaf(s, f1.y, 1.0f), EPSc));
        acc += __log2f(fmaxf(fmaf(s, f2.x, 1.0f), EPSc));
        acc += __log2f(fmaxf(fmaf(s, f2.y, 1.0f), EPSc));
        acc += __log2f(fmaxf(fmaf(s, f3.x, 1.0f), EPSc));
        acc += __log2f(fmaxf(fmaf(s, f3.y, 1.0f), EPSc));
    }

    // ---- Block reduction ----
    float v = acc;
    #pragma unroll
    for (int o = 16; o; o >>= 1) v += __shfl_down_sync(0xFFFFFFFFu, v, o);
    const int wid = tid >> 5, lane = tid & 31;
    if (lane == 0) red[wid] = v;
    __syncthreads();
    if (wid == 0) {
        float w = (lane < NTHREADS / 32) ? red[lane] : 0.0f;
        #pragma unroll
        for (int o = 8; o; o >>= 1) w += __shfl_down_sync(0xFFFFFFFFu, w, o);
        if (lane == 0) atomicAdd(&g_acc, (double)w);
    }

    // ---- Last-block-done: finalize + self-reset (keeps kernel graph-replayable) ----
    if (tid == 0) {
        __threadfence();
        unsigned int prev = atomicAdd(&g_cnt, 1u);
        if (prev == GRID - 1) {
            __threadfence();
            double S = *((volatile double*)&g_acc);
            // loss = 0.5*ln2*((M+K) - S/(B*T))
            double loss = 0.5 * 0.6931471805599453
                        * ((double)(Mc + Kc) - S / ((double)Bc * (double)Tc));
            out[0] = (float)loss;
            *((volatile double*)&g_acc) = 0.0;
            *((volatile unsigned int*)&g_cnt) = 0u;
            __threadfence();
        }
    }
}

extern "C" void kernel_launch(void* const* d_in, const int* in_sizes, int n_in,
                              void* d_out, int out_size) {
    const float* llrs        = (const float*)d_in[0];
    const int*   syndromes   = (const int*)d_in[1];
    const int*   observables = (const int*)d_in[2];
    const int*   chk_idx     = (const int*)d_in[3];
    // d_in[4] = chk_seg (unused: layout implied), d_in[5] = obs_idx, d_in[6] = obs_seg
    const int*   obs_idx     = (const int*)d_in[5];
    float* out = (float*)d_out;

    cudaFuncSetAttribute(decode_loss_kernel,
                         cudaFuncAttributeMaxDynamicSharedMemorySize, SMEM_BYTES);

    dim3 grid(NCHUNKS, Bc);
    decode_loss_kernel<<<grid, NTHREADS, SMEM_BYTES>>>(
        llrs, syndromes, observables, chk_idx, obs_idx, out);
}

// round 3
// speedup vs baseline: 3.6909x; 1.0851x over previous
#include <cuda_runtime.h>
#include <cuda_fp16.h>
#include <cstdint>

// Problem constants (fixed by the reference)
#define Bc 128
#define Tc 30
#define Nc 10000
#define Mc 5000
#define Kc 10
#define CHK_W 6
#define OBS_W 50
#define EPSc 1e-6f

#define NTHREADS 1024
#define ROWS 8
#define NCHUNKS 4                 // ceil(30/8)
#define GRID (Bc * NCHUNKS)       // 512 CTAs
#define NQ (Nc / 4)               // 2500 positions per j-plane

// Shared memory layout (bytes)
// tanh table: 4 planes (j = n mod 4) x 2500 uint4 (8 fp16 rows per position)
#define OFF_T8   0
#define SZ_T8    (Nc * 16)                  // 160000
#define OFF_CIDX (OFF_T8 + SZ_T8)           // 160000
#define SZ_CIDX  (Mc * CHK_W * 2)           // 60000 u16 (pre-transformed)
#define OFF_OIDX (OFF_CIDX + SZ_CIDX)       // 220000
#define SZ_OIDX  (Kc * OBS_W * 2)           // 1000 u16
#define OFF_RED  ((OFF_OIDX + SZ_OIDX + 15) & ~15)   // 221008
#define SMEM_BYTES (OFF_RED + 128)          // ~221136

__device__ double g_acc = 0.0;
__device__ unsigned int g_cnt = 0;

__device__ __forceinline__ __half2 H2(unsigned int u) {
    return *reinterpret_cast<const __half2*>(&u);
}
__device__ __forceinline__ unsigned int U2(__half2 h) {
    return *reinterpret_cast<const unsigned int*>(&h);
}
__device__ __forceinline__ unsigned int tanh_h2_u(__half2 v) {
    unsigned int r, x = U2(v);
    asm("tanh.approx.f16x2 %0, %1;" : "=r"(r) : "r"(x));
    return r;
}

__global__ __launch_bounds__(NTHREADS, 1)
void decode_loss_kernel(const float* __restrict__ llrs,
                        const int* __restrict__ syndromes,
                        const int* __restrict__ observables,
                        const int* __restrict__ chk_idx,
                        const int* __restrict__ obs_idx,
                        float* __restrict__ out) {
    extern __shared__ char smem[];
    uint4*          t8   = (uint4*)(smem + OFF_T8);
    unsigned short* cidx = (unsigned short*)(smem + OFF_CIDX);
    unsigned short* oidx = (unsigned short*)(smem + OFF_OIDX);
    float*          red  = (float*)(smem + OFF_RED);

    const int b     = blockIdx.y;
    const int t0    = blockIdx.x * ROWS;
    const int nrows = min(ROWS, Tc - t0);
    const int tid   = threadIdx.x;

    // ---- Stage indices, pre-transformed to plane layout:
    //      position n lives at plane (n&3), slot (n>>2) -> linear (n&3)*NQ + (n>>2)
    for (int i = tid; i < Mc * CHK_W; i += NTHREADS) {
        int v = __ldg(&chk_idx[i]);
        cidx[i] = (unsigned short)((v & 3) * NQ + (v >> 2));
    }
    for (int i = tid; i < Kc * OBS_W; i += NTHREADS) {
        int v = __ldg(&obs_idx[i]);
        oidx[i] = (unsigned short)((v & 3) * NQ + (v >> 2));
    }

    // ---- Phase 1: load 8 LLR rows as float4, tanh(x/2) in fp16x2, pack ----
    const float4* rb = (const float4*)(llrs + ((size_t)(b * Tc + t0)) * Nc);
    const __half2 h05 = __float2half2_rn(0.5f);
    for (int q = tid; q < NQ; q += NTHREADS) {
        unsigned int o[4][4];     // o[component j][row-pair rp]
        #pragma unroll
        for (int rp = 0; rp < 4; rp++) {
            const int r0 = 2 * rp, r1 = 2 * rp + 1;
            float4 a = (r0 < nrows) ? __ldg(&rb[(size_t)r0 * NQ + q])
                                    : make_float4(0.f, 0.f, 0.f, 0.f);
            float4 c = (r1 < nrows) ? __ldg(&rb[(size_t)r1 * NQ + q])
                                    : make_float4(0.f, 0.f, 0.f, 0.f);
            o[0][rp] = tanh_h2_u(__hmul2(__floats2half2_rn(a.x, c.x), h05));
            o[1][rp] = tanh_h2_u(__hmul2(__floats2half2_rn(a.y, c.y), h05));
            o[2][rp] = tanh_h2_u(__hmul2(__floats2half2_rn(a.z, c.z), h05));
            o[3][rp] = tanh_h2_u(__hmul2(__floats2half2_rn(a.w, c.w), h05));
        }
        #pragma unroll
        for (int j = 0; j < 4; j++)
            t8[j * NQ + q] = make_uint4(o[j][0], o[j][1], o[j][2], o[j][3]);
    }
    __syncthreads();

    const unsigned int* c32 = (const unsigned int*)cidx;
    const int* syn = syndromes + (size_t)b * Mc;

    // Accumulate S = sum over (check,row) of log2(1 + s*p).
    // loss = 0.5*ln2*((M+K) - S/(B*T)) folded at the end.
    float acc = 0.0f;

    // ---- Phase 2: check loop (M=5000, 6-wide products, 8 rows per LDS.128) ----
    for (int m = tid; m < Mc; m += NTHREADS) {
        unsigned int a0 = c32[3 * m];
        unsigned int a1 = c32[3 * m + 1];
        unsigned int a2 = c32[3 * m + 2];
        uint4 g0 = t8[a0 & 0xFFFF];
        uint4 g1 = t8[a0 >> 16];
        uint4 g2 = t8[a1 & 0xFFFF];
        uint4 g3 = t8[a1 >> 16];
        uint4 g4 = t8[a2 & 0xFFFF];
        uint4 g5 = t8[a2 >> 16];
        const float s = 1.0f - 2.0f * (float)__ldg(&syn[m]);

        __half2 p0 = __hmul2(__hmul2(H2(g0.x), H2(g1.x)),
                     __hmul2(__hmul2(H2(g2.x), H2(g3.x)), __hmul2(H2(g4.x), H2(g5.x))));
        __half2 p1 = __hmul2(__hmul2(H2(g0.y), H2(g1.y)),
                     __hmul2(__hmul2(H2(g2.y), H2(g3.y)), __hmul2(H2(g4.y), H2(g5.y))));
        __half2 p2 = __hmul2(__hmul2(H2(g0.z), H2(g1.z)),
                     __hmul2(__hmul2(H2(g2.z), H2(g3.z)), __hmul2(H2(g4.z), H2(g5.z))));
        __half2 p3 = __hmul2(__hmul2(H2(g0.w), H2(g1.w)),
                     __hmul2(__hmul2(H2(g2.w), H2(g3.w)), __hmul2(H2(g4.w), H2(g5.w))));

        float2 f0 = __half22float2(p0);
        float2 f1 = __half22float2(p1);
        float2 f2 = __half22float2(p2);
        float2 f3 = __half22float2(p3);

        float a00 = fmaxf(fmaf(s, f0.x, 1.0f), EPSc);
        float a01 = fmaxf(fmaf(s, f0.y, 1.0f), EPSc);
        float a02 = fmaxf(fmaf(s, f1.x, 1.0f), EPSc);
        float a03 = fmaxf(fmaf(s, f1.y, 1.0f), EPSc);
        float a04 = fmaxf(fmaf(s, f2.x, 1.0f), EPSc);
        float a05 = fmaxf(fmaf(s, f2.y, 1.0f), EPSc);
        float a06 = fmaxf(fmaf(s, f3.x, 1.0f), EPSc);
        float a07 = fmaxf(fmaf(s, f3.y, 1.0f), EPSc);

        // single log of the 8-arg product (args in [eps,2] -> product in [~0,256])
        float prod = ((a00 * a01) * (a02 * a03)) * ((a04 * a05) * (a06 * a07));
        acc += __log2f(prod);
    }

    // ---- Phase 3: observable loop (K=10, 50-wide products) ----
    if (tid < Kc) {
        const __half2 one2 = __float2half2_rn(1.0f);
        __half2 q0 = one2, q1 = one2, q2 = one2, q3 = one2;
        #pragma unroll
        for (int j = 0; j < OBS_W; j++) {
            uint4 g = t8[oidx[tid * OBS_W + j]];
            q0 = __hmul2(q0, H2(g.x));
            q1 = __hmul2(q1, H2(g.y));
            q2 = __hmul2(q2, H2(g.z));
            q3 = __hmul2(q3, H2(g.w));
        }
        const float s = 1.0f - 2.0f * (float)__ldg(&observables[(size_t)b * Kc + tid]);
        float2 f0 = __half22float2(q0);
        float2 f1 = __half22float2(q1);
        float2 f2 = __half22float2(q2);
        float2 f3 = __half22float2(q3);
        float a00 = fmaxf(fmaf(s, f0.x, 1.0f), EPSc);
        float a01 = fmaxf(fmaf(s, f0.y, 1.0f), EPSc);
        float a02 = fmaxf(fmaf(s, f1.x, 1.0f), EPSc);
        float a03 = fmaxf(fmaf(s, f1.y, 1.0f), EPSc);
        float a04 = fmaxf(fmaf(s, f2.x, 1.0f), EPSc);
        float a05 = fmaxf(fmaf(s, f2.y, 1.0f), EPSc);
        float a06 = fmaxf(fmaf(s, f3.x, 1.0f), EPSc);
        float a07 = fmaxf(fmaf(s, f3.y, 1.0f), EPSc);
        float prod = ((a00 * a01) * (a02 * a03)) * ((a04 * a05) * (a06 * a07));
        acc += __log2f(prod);
    }

    // ---- Block reduction ----
    float v = acc;
    #pragma unroll
    for (int o = 16; o; o >>= 1) v += __shfl_down_sync(0xFFFFFFFFu, v, o);
    const int wid = tid >> 5, lane = tid & 31;
    if (lane == 0) red[wid] = v;
    __syncthreads();
    if (wid == 0) {
        float w = (lane < NTHREADS / 32) ? red[lane] : 0.0f;
        #pragma unroll
        for (int o = 16; o; o >>= 1) w += __shfl_down_sync(0xFFFFFFFFu, w, o);
        if (lane == 0) atomicAdd(&g_acc, (double)w);
    }

    // ---- Last-block-done: finalize + self-reset (graph-replayable) ----
    if (tid == 0) {
        __threadfence();
        unsigned int prev = atomicAdd(&g_cnt, 1u);
        if (prev == GRID - 1) {
            __threadfence();
            double S = *((volatile double*)&g_acc);
            // loss = 0.5*ln2*((M+K) - S/(B*T))
            double loss = 0.5 * 0.6931471805599453
                        * ((double)(Mc + Kc) - S / ((double)Bc * (double)Tc));
            out[0] = (float)loss;
            *((volatile double*)&g_acc) = 0.0;
            *((volatile unsigned int*)&g_cnt) = 0u;
            __threadfence();
        }
    }
}

extern "C" void kernel_launch(void* const* d_in, const int* in_sizes, int n_in,
                              void* d_out, int out_size) {
    const float* llrs        = (const float*)d_in[0];
    const int*   syndromes   = (const int*)d_in[1];
    const int*   observables = (const int*)d_in[2];
    const int*   chk_idx     = (const int*)d_in[3];
    // d_in[4] = chk_seg (unused: layout implied), d_in[5] = obs_idx, d_in[6] = obs_seg
    const int*   obs_idx     = (const int*)d_in[5];
    float* out = (float*)d_out;

    cudaFuncSetAttribute(decode_loss_kernel,
                         cudaFuncAttributeMaxDynamicSharedMemorySize, SMEM_BYTES);

    dim3 grid(NCHUNKS, Bc);
    decode_loss_kernel<<<grid, NTHREADS, SMEM_BYTES>>>(
        llrs, syndromes, observables, chk_idx, obs_idx, out);
}

// round 4
// speedup vs baseline: 4.3013x; 1.1654x over previous
#include <cuda_runtime.h>
#include <cuda_fp16.h>
#include <cstdint>

// Problem constants (fixed by the reference)
#define Bc 128
#define Tc 30
#define Nc 10000
#define Mc 5000
#define Kc 10
#define CHK_W 6
#define OBS_W 50
#define EPSc 1e-6f

#define NTH   1024
#define NPROD 512            // warps 0-15: producers
#define NCONS 512            // warps 16-31: consumers
#define RPC   4              // rows per chunk
#define NCH   8              // ceil(30/4); last chunk has 2 rows
#define NQ    2500           // positions per j-plane (Nc/4)
#define GRID  Bc             // 128 persistent CTAs, one per b

// named barrier ids
#define BFULL0 2
#define BFULL1 3
#define BFREE0 4
#define BFREE1 5

// Shared memory layout (bytes)
#define OFF_BUF0 0
#define SZ_BUF   (Nc * 8)                    // 80000: uint2 per position (4 fp16 rows)
#define OFF_BUF1 (OFF_BUF0 + SZ_BUF)         // 80000
#define OFF_CIDX (OFF_BUF1 + SZ_BUF)         // 160000
#define SZ_CIDX  (Mc * CHK_W * 2)            // 60000 u16 (plane-transformed)
#define OFF_OIDX (OFF_CIDX + SZ_CIDX)        // 220000
#define SZ_OIDX  (Kc * OBS_W * 2)            // 1000
#define OFF_SYN  (OFF_OIDX + SZ_OIDX)        // 221000: s8 signs
#define OFF_OBSS (OFF_SYN + Mc)              // 226000: s8 obs signs (16B pad)
#define OFF_RED  ((OFF_OBSS + 16 + 15) & ~15)
#define SMEM_BYTES (OFF_RED + 128)           // ~226160

__device__ double g_acc = 0.0;
__device__ unsigned int g_cnt = 0;

__device__ __forceinline__ __half2 H2(unsigned int u) {
    return *reinterpret_cast<const __half2*>(&u);
}
__device__ __forceinline__ unsigned int U2(__half2 h) {
    return *reinterpret_cast<const unsigned int*>(&h);
}
__device__ __forceinline__ unsigned int tanh_h2_u(__half2 v) {
    unsigned int r, x = U2(v);
    asm("tanh.approx.f16x2 %0, %1;" : "=r"(r) : "r"(x));
    return r;
}
__device__ __forceinline__ void bar_sync(int id) {
    asm volatile("bar.sync %0, %1;" :: "r"(id), "n"(NTH) : "memory");
}
__device__ __forceinline__ void bar_arrive(int id) {
    asm volatile("bar.arrive %0, %1;" :: "r"(id), "n"(NTH) : "memory");
}
// pack 4 row-values of one position: .x = h2(r0,r1), .y = h2(r2,r3), tanh(x/2)
__device__ __forceinline__ uint2 pack_pos(float a, float b, float c, float d) {
    const __half2 h05 = __float2half2_rn(0.5f);
    uint2 o;
    o.x = tanh_h2_u(__hmul2(__floats2half2_rn(a, b), h05));
    o.y = tanh_h2_u(__hmul2(__floats2half2_rn(c, d), h05));
    return o;
}

__global__ __launch_bounds__(NTH, 1)
void decode_loss_kernel(const float* __restrict__ llrs,
                        const int* __restrict__ syndromes,
                        const int* __restrict__ observables,
                        const int* __restrict__ chk_idx,
                        const int* __restrict__ obs_idx,
                        float* __restrict__ out) {
    extern __shared__ char smem[];
    uint2*          buf0 = (uint2*)(smem + OFF_BUF0);
    uint2*          buf1 = (uint2*)(smem + OFF_BUF1);
    unsigned short* cidx = (unsigned short*)(smem + OFF_CIDX);
    unsigned short* oidx = (unsigned short*)(smem + OFF_OIDX);
    signed char*    ssyn = (signed char*)(smem + OFF_SYN);
    signed char*    sobs = (signed char*)(smem + OFF_OBSS);
    float*          red  = (float*)(smem + OFF_RED);

    const int b   = blockIdx.x;
    const int tid = threadIdx.x;

    // ---- Stage (once per CTA): transformed indices + sign tables ----
    for (int i = tid; i < Mc * CHK_W; i += NTH) {
        int v = __ldg(&chk_idx[i]);
        cidx[i] = (unsigned short)((v & 3) * NQ + (v >> 2));
    }
    for (int i = tid; i < Kc * OBS_W; i += NTH) {
        int v = __ldg(&obs_idx[i]);
        oidx[i] = (unsigned short)((v & 3) * NQ + (v >> 2));
    }
    for (int i = tid; i < Mc; i += NTH)
        ssyn[i] = (signed char)(1 - 2 * __ldg(&syndromes[(size_t)b * Mc + i]));
    if (tid < Kc)
        sobs[tid] = (signed char)(1 - 2 * __ldg(&observables[(size_t)b * Kc + tid]));
    __syncthreads();

    float acc = 0.0f;

    if (tid < NPROD) {
        // ================= PRODUCER =================
        const int tp = tid;
        for (int c = 0; c < NCH; c++) {
            if (c >= 2) bar_sync(BFREE0 + (c & 1));   // consumers done with this buf
            uint2* buf = (c & 1) ? buf1 : buf0;
            const int rows = min(RPC, Tc - RPC * c);
            const float4* rb = (const float4*)(llrs + ((size_t)b * Tc + (size_t)RPC * c) * Nc);

            for (int q = tp; q < NQ; q += 2 * NPROD) {
                const int q2 = q + NPROD;
                const bool g2 = (q2 < NQ);
                float4 z = make_float4(0.f, 0.f, 0.f, 0.f);
                // issue all 8 loads first (MLP)
                float4 v0 =              __ldg(&rb[0 * NQ + q]);
                float4 v1 = (rows > 1) ? __ldg(&rb[1 * NQ + q])  : z;
                float4 v2 = (rows > 2) ? __ldg(&rb[2 * NQ + q])  : z;
                float4 v3 = (rows > 3) ? __ldg(&rb[3 * NQ + q])  : z;
                float4 w0 = g2              ? __ldg(&rb[0 * NQ + q2]) : z;
                float4 w1 = (g2 && rows > 1) ? __ldg(&rb[1 * NQ + q2]) : z;
                float4 w2 = (g2 && rows > 2) ? __ldg(&rb[2 * NQ + q2]) : z;
                float4 w3 = (g2 && rows > 3) ? __ldg(&rb[3 * NQ + q2]) : z;

                buf[0 * NQ + q] = pack_pos(v0.x, v1.x, v2.x, v3.x);
                buf[1 * NQ + q] = pack_pos(v0.y, v1.y, v2.y, v3.y);
                buf[2 * NQ + q] = pack_pos(v0.z, v1.z, v2.z, v3.z);
                buf[3 * NQ + q] = pack_pos(v0.w, v1.w, v2.w, v3.w);
                if (g2) {
                    buf[0 * NQ + q2] = pack_pos(w0.x, w1.x, w2.x, w3.x);
                    buf[1 * NQ + q2] = pack_pos(w0.y, w1.y, w2.y, w3.y);
                    buf[2 * NQ + q2] = pack_pos(w0.z, w1.z, w2.z, w3.z);
                    buf[3 * NQ + q2] = pack_pos(w0.w, w1.w, w2.w, w3.w);
                }
            }
            bar_arrive(BFULL0 + (c & 1));
        }
    } else {
        // ================= CONSUMER =================
        const int tc = tid - NPROD;
        const unsigned int* c32 = (const unsigned int*)cidx;
        for (int c = 0; c < NCH; c++) {
            bar_sync(BFULL0 + (c & 1));
            const uint2* buf = (c & 1) ? buf1 : buf0;

            #pragma unroll 2
            for (int m = tc; m < Mc; m += NCONS) {
                unsigned int a0 = c32[3 * m];
                unsigned int a1 = c32[3 * m + 1];
                unsigned int a2 = c32[3 * m + 2];
                uint2 g0 = buf[a0 & 0xFFFF];
                uint2 g1 = buf[a0 >> 16];
                uint2 g2 = buf[a1 & 0xFFFF];
                uint2 g3 = buf[a1 >> 16];
                uint2 g4 = buf[a2 & 0xFFFF];
                uint2 g5 = buf[a2 >> 16];
                const float s = (float)ssyn[m];

                __half2 pa = __hmul2(__hmul2(H2(g0.x), H2(g1.x)),
                             __hmul2(__hmul2(H2(g2.x), H2(g3.x)), __hmul2(H2(g4.x), H2(g5.x))));
                __half2 pb = __hmul2(__hmul2(H2(g0.y), H2(g1.y)),
                             __hmul2(__hmul2(H2(g2.y), H2(g3.y)), __hmul2(H2(g4.y), H2(g5.y))));
                float2 f0 = __half22float2(pa);
                float2 f1 = __half22float2(pb);
                float a00 = fmaxf(fmaf(s, f0.x, 1.0f), EPSc);
                float a01 = fmaxf(fmaf(s, f0.y, 1.0f), EPSc);
                float a02 = fmaxf(fmaf(s, f1.x, 1.0f), EPSc);
                float a03 = fmaxf(fmaf(s, f1.y, 1.0f), EPSc);
                acc += __log2f((a00 * a01) * (a02 * a03));
            }

            if (tc < Kc) {
                const __half2 one2 = __float2half2_rn(1.0f);
                __half2 qa = one2, qb = one2;
                #pragma unroll
                for (int j = 0; j < OBS_W; j++) {
                    uint2 g = buf[oidx[tc * OBS_W + j]];
                    qa = __hmul2(qa, H2(g.x));
                    qb = __hmul2(qb, H2(g.y));
                }
                const float s = (float)sobs[tc];
                float2 f0 = __half22float2(qa);
                float2 f1 = __half22float2(qb);
                float a00 = fmaxf(fmaf(s, f0.x, 1.0f), EPSc);
                float a01 = fmaxf(fmaf(s, f0.y, 1.0f), EPSc);
                float a02 = fmaxf(fmaf(s, f1.x, 1.0f), EPSc);
                float a03 = fmaxf(fmaf(s, f1.y, 1.0f), EPSc);
                acc += __log2f((a00 * a01) * (a02 * a03));
            }

            // release the buffer for reuse (skip last two: no producer will wait)
            if (c < NCH - 2) bar_arrive(BFREE0 + (c & 1));
        }
    }

    // ---- Block reduction (producers contribute 0) ----
    __syncthreads();
    float v = acc;
    #pragma unroll
    for (int o = 16; o; o >>= 1) v += __shfl_down_sync(0xFFFFFFFFu, v, o);
    const int wid = tid >> 5, lane = tid & 31;
    if (lane == 0) red[wid] = v;
    __syncthreads();
    if (wid == 0) {
        float w = (lane < NTH / 32) ? red[lane] : 0.0f;
        #pragma unroll
        for (int o = 16; o; o >>= 1) w += __shfl_down_sync(0xFFFFFFFFu, w, o);
        if (lane == 0) atomicAdd(&g_acc, (double)w);
    }

    // ---- Last-block-done: finalize + self-reset (graph-replayable) ----
    if (tid == 0) {
        __threadfence();
        unsigned int prev = atomicAdd(&g_cnt, 1u);
        if (prev == GRID - 1) {
            __threadfence();
            double S = *((volatile double*)&g_acc);
            // loss = 0.5*ln2*((M+K) - S/(B*T))
            double loss = 0.5 * 0.6931471805599453
                        * ((double)(Mc + Kc) - S / ((double)Bc * (double)Tc));
            out[0] = (float)loss;
            *((volatile double*)&g_acc) = 0.0;
            *((volatile unsigned int*)&g_cnt) = 0u;
            __threadfence();
        }
    }
}

extern "C" void kernel_launch(void* const* d_in, const int* in_sizes, int n_in,
                              void* d_out, int out_size) {
    const float* llrs        = (const float*)d_in[0];
    const int*   syndromes   = (const int*)d_in[1];
    const int*   observables = (const int*)d_in[2];
    const int*   chk_idx     = (const int*)d_in[3];
    // d_in[4] = chk_seg (unused: layout implied), d_in[5] = obs_idx, d_in[6] = obs_seg
    const int*   obs_idx     = (const int*)d_in[5];
    float* out = (float*)d_out;

    cudaFuncSetAttribute(decode_loss_kernel,
                         cudaFuncAttributeMaxDynamicSharedMemorySize, SMEM_BYTES);

    decode_loss_kernel<<<GRID, NTH, SMEM_BYTES>>>(
        llrs, syndromes, observables, chk_idx, obs_idx, out);
}